// round 4
// baseline (speedup 1.0000x reference)
#include <cuda_runtime.h>
#include <math.h>

#define IMG_H 1088
#define IMG_W 1920
#define BATCH 8
#define TILE  32
#define NT    256

#define WI 46   // s_img row stride (floats), even -> float2 aligned
#define WT 40   // s_tmp row stride, even -> float2 aligned
#define WB 39   // s_blur row stride
#define WM 37   // s_mag row stride
#define WN 35   // s_thin row stride

// smem float offsets with aliasing:
//   s_img  44x46 = 2024  -> aliased by s_mag (36x37=1332) after stage 1a
//   s_tmp  44x40 = 1760  -> aliased by s_thin (34x35=1190) after stage 1b
//   s_blur 38x39 = 1482
#define OFF_IMG  0
#define OFF_TMP  2024
#define OFF_BLUR 3784
#define SM_FLOATS 5266

// cephes-style atan2, max err ~1e-7 rad
__device__ __forceinline__ float fast_atan2(float y, float x) {
    float ax = fabsf(x), ay = fabsf(y);
    float mx = fmaxf(ax, ay), mn = fminf(ax, ay);
    float t = __fdividef(mn, mx);
    if (mx == 0.0f) t = 0.0f;
    bool red = t > 0.4142135624f;
    float tr = __fdividef(t - 1.0f, t + 1.0f);
    float u = red ? tr : t;
    float z = u * u;
    float p = ((8.05374449538e-2f * z - 1.38776856032e-1f) * z
               + 1.99777106478e-1f) * z - 3.33329491539e-1f;
    float a = fmaf(p * z, u, u);
    if (red) a += 0.7853981634f;
    if (ay > ax) a = 1.5707963268f - a;
    if (x < 0.0f) a = 3.1415926536f - a;
    return (y < 0.0f) ? -a : a;
}

__global__ __launch_bounds__(NT) void canny_kernel(
    const float* __restrict__ img,
    const float* __restrict__ gk,
    float* __restrict__ out,
    long long N)
{
    __shared__ __align__(16) float sbuf[SM_FLOATS];
    __shared__ float s_r[7], s_c[7];
    float* s_img  = sbuf + OFF_IMG;
    float* s_tmp  = sbuf + OFF_TMP;
    float* s_blur = sbuf + OFF_BLUR;
    float* s_mag  = sbuf + OFF_IMG;   // alias: img dead after stage 1a
    float* s_thin = sbuf + OFF_TMP;   // alias: tmp dead after stage 1b

    const int tid = threadIdx.x;
    const int bx = blockIdx.x * TILE;
    const int by = blockIdx.y * TILE;
    const int b  = blockIdx.z;
    const float* ip = img + (long long)b * (IMG_H * IMG_W);
    const long long pbase = (long long)b * (IMG_H * IMG_W);

    if (tid < 7) {
        // gaussian is a normalized outer product: k[i][j] = k[i][4]*k[4][j]/k[4][4]
        float s = sqrtf(gk[4 * 7 + 4]);
        s_r[tid] = gk[tid * 7 + 4] / s;   // vertical factor
        s_c[tid] = gk[4 * 7 + tid] / s;   // horizontal factor
    }

    // ---- stage 0: load img tile 44x44, zero padded outside image ----
    for (int idx = tid; idx < 44 * 44; idx += NT) {
        int r = idx / 44, c = idx - r * 44;
        int gy = by - 6 + r, gx = bx - 6 + c;
        float v = 0.0f;
        if ((unsigned)gy < IMG_H && (unsigned)gx < IMG_W)
            v = ip[(long long)gy * IMG_W + gx];
        s_img[r * WI + c] = v;
    }
    __syncthreads();

    const float c0 = s_c[0], c1 = s_c[1], c2 = s_c[2], c3 = s_c[3],
                c4 = s_c[4], c5 = s_c[5], c6 = s_c[6];
    const float r0 = s_r[0], r1 = s_r[1], r2 = s_r[2], r3 = s_r[3],
                r4 = s_r[4], r5 = s_r[5], r6 = s_r[6];

    // ---- stage 1a: horizontal 7-tap, float2-blocked: 44 rows x 19 pairs ----
    {
        const float2* img2 = (const float2*)(sbuf + OFF_IMG);
        float2* tmp2 = (float2*)(sbuf + OFF_TMP);
        for (int idx = tid; idx < 44 * 19; idx += NT) {
            int r = idx / 19, p = idx - r * 19;
            const float2* row = img2 + r * (WI / 2) + p;
            float2 A = row[0], B = row[1], C = row[2], D = row[3];
            float o0 = c0*A.x + c1*A.y + c2*B.x + c3*B.y + c4*C.x + c5*C.y + c6*D.x;
            float o1 = c0*A.y + c1*B.x + c2*B.y + c3*C.x + c4*C.y + c5*D.x + c6*D.y;
            tmp2[r * (WT / 2) + p] = make_float2(o0, o1);
        }
    }
    __syncthreads();

    // ---- stage 1b: vertical 7-tap -> blur 38x38 (+ write blur plane) ----
    for (int idx = tid; idx < 38 * 10; idx += NT) {
        int c = idx % 38, rb = idx / 38;
        int rr = rb * 4;
        float tv[10];
        #pragma unroll
        for (int i = 0; i < 10; i++)
            tv[i] = (rr + i < 44) ? s_tmp[(rr + i) * WT + c] : 0.0f;
        int gx = bx - 3 + c;
        bool cok  = (unsigned)gx < IMG_W;
        bool cint = (c >= 3) && (c < 35);
        #pragma unroll
        for (int i = 0; i < 4; i++) {
            int r = rr + i;
            if (r < 38) {
                float v = r0*tv[i] + r1*tv[i+1] + r2*tv[i+2] + r3*tv[i+3]
                        + r4*tv[i+4] + r5*tv[i+5] + r6*tv[i+6];
                int gy = by - 3 + r;
                bool ok = cok && (unsigned)gy < IMG_H;
                float vm = ok ? v : 0.0f;
                s_blur[r * WB + c] = vm;
                if (cint && r >= 3 && r < 35)
                    out[pbase + (long long)gy * IMG_W + gx] = vm;
            }
        }
    }
    __syncthreads();

    // ---- stage 2: sobel -> mag (+ write mag & orient planes) ----
    for (int idx = tid; idx < 36 * 9; idx += NT) {
        int c = idx % 36, rb = idx / 36;
        int rr = rb * 4;
        float p6[6], q6[6];   // p = colL - colR ; q = colL + 2*colM + colR
        #pragma unroll
        for (int i = 0; i < 6; i++) {
            const float* row = s_blur + (rr + i) * WB + c;
            float a = row[0], m = row[1], d = row[2];
            p6[i] = a - d;
            q6[i] = a + 2.0f * m + d;
        }
        int gxp = bx - 2 + c;
        bool cok  = (unsigned)gxp < IMG_W;
        bool cint = (c >= 2) && (c < 34);
        #pragma unroll
        for (int i = 0; i < 4; i++) {
            int r = rr + i;
            float gxv = p6[i] + 2.0f * p6[i+1] + p6[i+2];
            float gyv = q6[i] - q6[i+2];
            float m = sqrtf(gxv * gxv + gyv * gyv);
            int gy = by - 2 + r;
            bool ok = cok && (unsigned)gy < IMG_H;
            float mm = ok ? m : 0.0f;
            s_mag[r * WM + c] = mm;
            if (cint && r >= 2 && r < 34) {
                long long o = pbase + (long long)gy * IMG_W + gxp;
                out[N + o]     = mm;
                out[2 * N + o] = fast_atan2(gyv, gxv);
            }
        }
    }
    __syncthreads();

    // ---- stage 3: non-max suppression -> thin (+ write thin plane) ----
    for (int idx = tid; idx < 34 * 9; idx += NT) {
        int c = idx % 34, rb = idx / 34;
        int rr = rb * 4;
        float pp[6], qq[6], mm[6];
        #pragma unroll
        for (int i = 0; i < 6; i++) {
            float a = 0.0f, m = 0.0f, d = 0.0f;
            if (rr + i < 36) {
                const float* row = s_mag + (rr + i) * WM + c;
                a = row[0]; m = row[1]; d = row[2];
            }
            pp[i] = a - d;
            qq[i] = a + 2.0f * m + d;
            mm[i] = m;
        }
        int gxp = bx - 1 + c;
        bool cok  = (unsigned)gxp < IMG_W;
        bool cint = (c >= 1) && (c < 33);
        #pragma unroll
        for (int i = 0; i < 4; i++) {
            int r = rr + i;
            if (r < 34) {
                float sx = pp[i] + 2.0f * pp[i+1] + pp[i+2];
                float sy = qq[i] - qq[i+2];
                float m  = mm[i+1];
                float v = (m >= sx && m >= sy) ? m : 0.0f;
                int gy = by - 1 + r;
                bool ok = cok && (unsigned)gy < IMG_H;
                float vt = ok ? v : 0.0f;
                s_thin[r * WN + c] = vt;
                if (cint && r >= 1 && r < 33)
                    out[3 * N + pbase + (long long)gy * IMG_W + gxp] = vt;
            }
        }
    }
    __syncthreads();

    // ---- stage 4: hysteresis -> edges plane; 1 column x 4 rows per thread ----
    {
        int c  = tid & 31;
        int rb = tid >> 5;
        int rr = rb * 4;

        float tw[6][3];
        #pragma unroll
        for (int i = 0; i < 6; i++) {
            const float* row = s_thin + (rr + i) * WN + c;
            tw[i][0] = row[0]; tw[i][1] = row[1]; tw[i][2] = row[2];
        }
        int sb[6][3];
        #pragma unroll
        for (int i = 0; i < 6; i++) {
            sb[i][0] = tw[i][0] > 3.0f;
            sb[i][1] = tw[i][1] > 3.0f;
            sb[i][2] = tw[i][2] > 3.0f;
        }

        long long obase = 4 * N + pbase
                        + (long long)(by + rr) * IMG_W + (bx + c);
        #pragma unroll
        for (int i = 0; i < 4; i++) {
            float tc = tw[i + 1][1];
            bool strong = tc > 3.0f;
            bool weak   = (tc > 1.0f) && (tc <= 3.0f);
            int full9 = sb[i][0] + sb[i][1] + sb[i][2]
                      + sb[i+1][0] + sb[i+1][1] + sb[i+1][2]
                      + sb[i+2][0] + sb[i+2][1] + sb[i+2][2];
            // conv with hyst_k (center -8) > 0  <=>  full9 - 9*center_strong > 0
            bool sn   = (full9 - 9 * sb[i+1][1]) > 0;
            bool edge = strong || (weak && sn);
            out[obase + (long long)i * IMG_W] = edge ? 1.0f : 0.0f;
        }
    }
}

extern "C" void kernel_launch(void* const* d_in, const int* in_sizes, int n_in,
                              void* d_out, int out_size) {
    const float* img = (const float*)d_in[0];
    const float* gk  = (const float*)d_in[1];
    float* out = (float*)d_out;
    long long N = (long long)out_size / 5;   // 5 concatenated planes
    dim3 grid(IMG_W / TILE, IMG_H / TILE, BATCH);
    canny_kernel<<<grid, NT>>>(img, gk, out, N);
}

// round 5
// speedup vs baseline: 1.3407x; 1.3407x over previous
#include <cuda_runtime.h>
#include <math.h>

#define IMG_H 1088
#define IMG_W 1920
#define BATCH 8
#define TILE  32
#define NT    256

#define WI 46   // s_img row stride (even -> float2 aligned)
#define WT 40   // s_tmp row stride (even -> float2 aligned)
#define WB 39   // s_blur row stride (odd)
#define WM 37   // s_mag/s_gx/s_gy row stride (odd)
#define WN 35   // s_thin row stride (odd)

// smem float offsets (aliasing dead regions):
//   s_img  44x46 = 2024  -> aliased by s_gx (36x37=1332) after stage 1a
//   s_tmp  44x40 = 1760  -> aliased by s_gy (36x37=1332) after stage 1b
//   s_blur 38x39 = 1482
//   s_mag  36x37 = 1332
//   s_thin 34x35 = 1190
#define OFF_IMG  0
#define OFF_TMP  2024
#define OFF_BLUR 3784
#define OFF_MAG  5266
#define OFF_THIN 6598
#define SM_FLOATS 7788

// cephes-style atan2, max err ~1e-7 rad
__device__ __forceinline__ float fast_atan2(float y, float x) {
    float ax = fabsf(x), ay = fabsf(y);
    float mx = fmaxf(ax, ay), mn = fminf(ax, ay);
    float t = __fdividef(mn, mx);
    if (mx == 0.0f) t = 0.0f;
    bool red = t > 0.4142135624f;
    float tr = __fdividef(t - 1.0f, t + 1.0f);
    float u = red ? tr : t;
    float z = u * u;
    float p = ((8.05374449538e-2f * z - 1.38776856032e-1f) * z
               + 1.99777106478e-1f) * z - 3.33329491539e-1f;
    float a = fmaf(p * z, u, u);
    if (red) a += 0.7853981634f;
    if (ay > ax) a = 1.5707963268f - a;
    if (x < 0.0f) a = 3.1415926536f - a;
    return (y < 0.0f) ? -a : a;
}

__global__ __launch_bounds__(NT) void canny_kernel(
    const float* __restrict__ img,
    const float* __restrict__ gk,
    float* __restrict__ out,
    long long N)
{
    __shared__ __align__(16) float sbuf[SM_FLOATS];
    __shared__ float s_r[7], s_c[7];
    float* s_img  = sbuf + OFF_IMG;
    float* s_tmp  = sbuf + OFF_TMP;
    float* s_blur = sbuf + OFF_BLUR;
    float* s_mag  = sbuf + OFF_MAG;
    float* s_thin = sbuf + OFF_THIN;
    float* s_gx   = sbuf + OFF_IMG;   // alias: img dead after stage 1a
    float* s_gy   = sbuf + OFF_TMP;   // alias: tmp dead after stage 1b

    const int tid = threadIdx.x;
    const int bx = blockIdx.x * TILE;
    const int by = blockIdx.y * TILE;
    const int b  = blockIdx.z;
    const float* ip = img + (long long)b * (IMG_H * IMG_W);

    if (tid < 7) {
        // gaussian is a normalized outer product: k[i][j] = k[i][4]*k[4][j]/k[4][4]
        float s = sqrtf(gk[4 * 7 + 4]);
        s_r[tid] = gk[tid * 7 + 4] / s;   // vertical factor
        s_c[tid] = gk[4 * 7 + tid] / s;   // horizontal factor
    }

    // ---- stage 0: load img tile 44x44, zero padded outside image ----
    for (int idx = tid; idx < 44 * 44; idx += NT) {
        int r = idx / 44, c = idx - r * 44;
        int gy = by - 6 + r, gx = bx - 6 + c;
        float v = 0.0f;
        if ((unsigned)gy < IMG_H && (unsigned)gx < IMG_W)
            v = ip[(long long)gy * IMG_W + gx];
        s_img[r * WI + c] = v;
    }
    __syncthreads();

    const float c0 = s_c[0], c1 = s_c[1], c2 = s_c[2], c3 = s_c[3],
                c4 = s_c[4], c5 = s_c[5], c6 = s_c[6];
    const float r0 = s_r[0], r1 = s_r[1], r2 = s_r[2], r3 = s_r[3],
                r4 = s_r[4], r5 = s_r[5], r6 = s_r[6];

    // ---- stage 1a: horizontal 7-tap, float2-blocked: 44 rows x 19 pairs ----
    {
        const float2* img2 = (const float2*)(sbuf + OFF_IMG);
        float2* tmp2 = (float2*)(sbuf + OFF_TMP);
        for (int idx = tid; idx < 44 * 19; idx += NT) {
            int r = idx / 19, p = idx - r * 19;
            const float2* row = img2 + r * (WI / 2) + p;
            float2 A = row[0], B = row[1], C = row[2], D = row[3];
            float o0 = c0*A.x + c1*A.y + c2*B.x + c3*B.y + c4*C.x + c5*C.y + c6*D.x;
            float o1 = c0*A.y + c1*B.x + c2*B.y + c3*C.x + c4*C.y + c5*D.x + c6*D.y;
            tmp2[r * (WT / 2) + p] = make_float2(o0, o1);
        }
    }
    __syncthreads();

    // ---- stage 1b: vertical 7-tap -> blur 38x38, 4-row blocks, zero outside ----
    for (int idx = tid; idx < 38 * 10; idx += NT) {
        int c = idx % 38, rb = idx / 38;
        int rr = rb * 4;
        float tv[10];
        #pragma unroll
        for (int i = 0; i < 10; i++)
            tv[i] = (rr + i < 44) ? s_tmp[(rr + i) * WT + c] : 0.0f;
        int gx = bx - 3 + c;
        bool cok = (unsigned)gx < IMG_W;
        #pragma unroll
        for (int i = 0; i < 4; i++) {
            int r = rr + i;
            if (r < 38) {
                float v = r0*tv[i] + r1*tv[i+1] + r2*tv[i+2] + r3*tv[i+3]
                        + r4*tv[i+4] + r5*tv[i+5] + r6*tv[i+6];
                int gy = by - 3 + r;
                bool ok = cok && (unsigned)gy < IMG_H;
                s_blur[r * WB + c] = ok ? v : 0.0f;
            }
        }
    }
    __syncthreads();

    // ---- stage 2: sobel -> mag (masked) + gx,gy cached; 36x36, 4-row blocks ----
    for (int idx = tid; idx < 36 * 9; idx += NT) {
        int c = idx % 36, rb = idx / 36;
        int rr = rb * 4;
        float p6[6], q6[6];   // p = colL - colR ; q = colL + 2*colM + colR
        #pragma unroll
        for (int i = 0; i < 6; i++) {
            const float* row = s_blur + (rr + i) * WB + c;
            float a = row[0], m = row[1], d = row[2];
            p6[i] = a - d;
            q6[i] = a + 2.0f * m + d;
        }
        int gxp = bx - 2 + c;
        bool cok = (unsigned)gxp < IMG_W;
        #pragma unroll
        for (int i = 0; i < 4; i++) {
            int r = rr + i;
            float gxv = p6[i] + 2.0f * p6[i+1] + p6[i+2];
            float gyv = q6[i] - q6[i+2];
            float m = sqrtf(gxv * gxv + gyv * gyv);
            int gy = by - 2 + r;
            bool ok = cok && (unsigned)gy < IMG_H;
            s_mag[r * WM + c] = ok ? m : 0.0f;
            s_gx [r * WM + c] = gxv;
            s_gy [r * WM + c] = gyv;
        }
    }
    __syncthreads();

    // ---- stage 3: non-max suppression -> thin 34x34, 4-row blocks ----
    for (int idx = tid; idx < 34 * 9; idx += NT) {
        int c = idx % 34, rb = idx / 34;
        int rr = rb * 4;
        float pp[6], qq[6], mm[6];
        #pragma unroll
        for (int i = 0; i < 6; i++) {
            float a = 0.0f, m = 0.0f, d = 0.0f;
            if (rr + i < 36) {
                const float* row = s_mag + (rr + i) * WM + c;
                a = row[0]; m = row[1]; d = row[2];
            }
            pp[i] = a - d;
            qq[i] = a + 2.0f * m + d;
            mm[i] = m;
        }
        int gxp = bx - 1 + c;
        bool cok = (unsigned)gxp < IMG_W;
        #pragma unroll
        for (int i = 0; i < 4; i++) {
            int r = rr + i;
            if (r < 34) {
                float sx = pp[i] + 2.0f * pp[i+1] + pp[i+2];
                float sy = qq[i] - qq[i+2];
                float m  = mm[i+1];
                float v = (m >= sx && m >= sy) ? m : 0.0f;
                int gy = by - 1 + r;
                bool ok = cok && (unsigned)gy < IMG_H;
                s_thin[r * WN + c] = ok ? v : 0.0f;
            }
        }
    }
    __syncthreads();

    // ---- stage 4: hysteresis + 5 plane writes; 1 column x 4 rows per thread ----
    {
        int c  = tid & 31;        // output column
        int rb = tid >> 5;        // row block (0..7)
        int rr = rb * 4;

        int sb[6][3];
        #pragma unroll
        for (int i = 0; i < 6; i++) {
            const float* row = s_thin + (rr + i) * WN + c;
            sb[i][0] = row[0] > 3.0f;
            sb[i][1] = row[1] > 3.0f;
            sb[i][2] = row[2] > 3.0f;
        }

        long long obase = (long long)b * (IMG_H * IMG_W)
                        + (long long)(by + rr) * IMG_W + (bx + c);
        #pragma unroll
        for (int i = 0; i < 4; i++) {
            float blv = s_blur[(rr + i + 3) * WB + (c + 3)];
            float mv  = s_mag [(rr + i + 2) * WM + (c + 2)];
            float gxv = s_gx  [(rr + i + 2) * WM + (c + 2)];
            float gyv = s_gy  [(rr + i + 2) * WM + (c + 2)];
            float tc  = s_thin[(rr + i + 1) * WN + (c + 1)];

            bool strong = tc > 3.0f;
            bool weak   = (tc > 1.0f) && (tc <= 3.0f);
            int full9 = sb[i][0] + sb[i][1] + sb[i][2]
                      + sb[i+1][0] + sb[i+1][1] + sb[i+1][2]
                      + sb[i+2][0] + sb[i+2][1] + sb[i+2][2];
            // conv with hyst_k (center -8) > 0  <=>  full9 - 9*center_strong > 0
            bool sn   = (full9 - 9 * sb[i+1][1]) > 0;
            bool edge = strong || (weak && sn);

            long long o = obase + (long long)i * IMG_W;
            out[o]         = blv;
            out[N + o]     = mv;
            out[2 * N + o] = fast_atan2(gyv, gxv);
            out[3 * N + o] = tc;
            out[4 * N + o] = edge ? 1.0f : 0.0f;
        }
    }
}

extern "C" void kernel_launch(void* const* d_in, const int* in_sizes, int n_in,
                              void* d_out, int out_size) {
    const float* img = (const float*)d_in[0];
    const float* gk  = (const float*)d_in[1];
    float* out = (float*)d_out;
    long long N = (long long)out_size / 5;   // 5 concatenated planes
    dim3 grid(IMG_W / TILE, IMG_H / TILE, BATCH);
    canny_kernel<<<grid, NT>>>(img, gk, out, N);
}

// round 6
// speedup vs baseline: 1.6670x; 1.2434x over previous
#include <cuda_runtime.h>
#include <math.h>

#define IMG_H 1088
#define IMG_W 1920
#define BATCH 8
#define TILE  32
#define NT    256

#define WI 48   // s_img stride (float4-aligned)
#define WT 40   // s_tmp stride (float2)
#define WB 40   // s_blur stride (float2)
#define WM 38   // s_mag/gx/gy stride (float2)
#define WN 36   // s_thin stride (float2)

// smem float offsets (aliasing dead regions):
//   s_img  44x48 = 2112  -> aliased by s_gx (36x38=1368) after stage 1a
//   s_tmp  44x40 = 1760  -> aliased by s_gy (36x38=1368) after stage 1b
//   s_blur 38x40 = 1520
//   s_mag  36x38 = 1368
//   s_thin 34x36 = 1224
#define OFF_IMG  0
#define OFF_TMP  2112
#define OFF_BLUR 3872
#define OFF_MAG  5392
#define OFF_THIN 6760
#define SM_FLOATS 7984

// cephes-style atan2, max err ~1e-7 rad
__device__ __forceinline__ float fast_atan2(float y, float x) {
    float ax = fabsf(x), ay = fabsf(y);
    float mx = fmaxf(ax, ay), mn = fminf(ax, ay);
    float t = __fdividef(mn, mx);
    if (mx == 0.0f) t = 0.0f;
    bool red = t > 0.4142135624f;
    float tr = __fdividef(t - 1.0f, t + 1.0f);
    float u = red ? tr : t;
    float z = u * u;
    float p = ((8.05374449538e-2f * z - 1.38776856032e-1f) * z
               + 1.99777106478e-1f) * z - 3.33329491539e-1f;
    float a = fmaf(p * z, u, u);
    if (red) a += 0.7853981634f;
    if (ay > ax) a = 1.5707963268f - a;
    if (x < 0.0f) a = 3.1415926536f - a;
    return (y < 0.0f) ? -a : a;
}

__global__ __launch_bounds__(NT) void canny_kernel(
    const float* __restrict__ img,
    const float* __restrict__ gk,
    float* __restrict__ out,
    long long N)
{
    __shared__ __align__(16) float sbuf[SM_FLOATS];
    __shared__ float s_r[7], s_c[7];
    float* s_img  = sbuf + OFF_IMG;
    float* s_blur = sbuf + OFF_BLUR;
    float* s_mag  = sbuf + OFF_MAG;
    float* s_thin = sbuf + OFF_THIN;
    float* s_gx   = sbuf + OFF_IMG;   // alias: img dead after stage 1a
    float* s_gy   = sbuf + OFF_TMP;   // alias: tmp dead after stage 1b

    const int tid = threadIdx.x;
    const int bx = blockIdx.x * TILE;
    const int by = blockIdx.y * TILE;
    const int b  = blockIdx.z;
    const float* ip = img + (long long)b * (IMG_H * IMG_W);

    if (tid < 7) {
        // gaussian is a normalized outer product: k[i][j] = k[i][4]*k[4][j]/k[4][4]
        float s = sqrtf(gk[4 * 7 + 4]);
        s_r[tid] = gk[tid * 7 + 4] / s;   // vertical factor
        s_c[tid] = gk[4 * 7 + tid] / s;   // horizontal factor
    }

    // ---- stage 0: load img cols [bx-8, bx+40) x rows [by-6, by+38) ----
    // local col c holds global col bx-8+c; stage 1a reads from local col 2.
    if (bx >= 32 && bx + 40 <= IMG_W) {
        // fast path: all 48 cols in range; float4 loads (bx-8 is 8-float aligned)
        float4* img4 = (float4*)s_img;
        for (int idx = tid; idx < 44 * 12; idx += NT) {
            int r = idx / 12, v = idx - r * 12;
            int gy = by - 6 + r;
            float4 val = make_float4(0.f, 0.f, 0.f, 0.f);
            if ((unsigned)gy < IMG_H)
                val = *(const float4*)(ip + (long long)gy * IMG_W + (bx - 8) + 4 * v);
            img4[r * (WI / 4) + v] = val;
        }
    } else {
        for (int idx = tid; idx < 44 * 48; idx += NT) {
            int r = idx / 48, c = idx - r * 48;
            int gy = by - 6 + r, gx = bx - 8 + c;
            float v = 0.0f;
            if ((unsigned)gy < IMG_H && (unsigned)gx < IMG_W)
                v = ip[(long long)gy * IMG_W + gx];
            s_img[r * WI + c] = v;
        }
    }
    __syncthreads();

    const float c0 = s_c[0], c1 = s_c[1], c2 = s_c[2], c3 = s_c[3],
                c4 = s_c[4], c5 = s_c[5], c6 = s_c[6];
    const float r0 = s_r[0], r1 = s_r[1], r2 = s_r[2], r3 = s_r[3],
                r4 = s_r[4], r5 = s_r[5], r6 = s_r[6];

    // ---- stage 1a: horizontal 7-tap, 44 rows x 19 col-pairs ----
    {
        const float2* img2 = (const float2*)s_img;
        float2* tmp2 = (float2*)(sbuf + OFF_TMP);
        for (int idx = tid; idx < 44 * 19; idx += NT) {
            int r = idx / 19, p = idx - r * 19;
            // output cols 2p,2p+1 need img local cols 2p+2 .. 2p+9
            const float2* row = img2 + r * (WI / 2) + (p + 1);
            float2 A = row[0], B = row[1], C = row[2], D = row[3];
            float o0 = c0*A.x + c1*A.y + c2*B.x + c3*B.y + c4*C.x + c5*C.y + c6*D.x;
            float o1 = c0*A.y + c1*B.x + c2*B.y + c3*C.x + c4*C.y + c5*D.x + c6*D.y;
            tmp2[r * (WT / 2) + p] = make_float2(o0, o1);
        }
    }
    __syncthreads();

    // ---- stage 1b: vertical 7-tap -> blur 38x38; 19 pairs x 10 row-blocks ----
    {
        const float2* tmp2 = (const float2*)(sbuf + OFF_TMP);
        float2* blur2 = (float2*)s_blur;
        for (int idx = tid; idx < 19 * 10; idx += NT) {
            int p = idx % 19, rb = idx / 19;
            int rr = rb * 4;
            float2 tv[10];
            #pragma unroll
            for (int i = 0; i < 10; i++)
                tv[i] = (rr + i < 44) ? tmp2[(rr + i) * (WT / 2) + p]
                                      : make_float2(0.f, 0.f);
            int gx0 = bx - 3 + 2 * p;
            bool cok0 = (unsigned)gx0 < IMG_W;
            bool cok1 = (unsigned)(gx0 + 1) < IMG_W;
            #pragma unroll
            for (int i = 0; i < 4; i++) {
                int r = rr + i;
                if (r < 38) {
                    float vx = r0*tv[i].x + r1*tv[i+1].x + r2*tv[i+2].x + r3*tv[i+3].x
                             + r4*tv[i+4].x + r5*tv[i+5].x + r6*tv[i+6].x;
                    float vy = r0*tv[i].y + r1*tv[i+1].y + r2*tv[i+2].y + r3*tv[i+3].y
                             + r4*tv[i+4].y + r5*tv[i+5].y + r6*tv[i+6].y;
                    int gy = by - 3 + r;
                    bool rok = (unsigned)gy < IMG_H;
                    float2 o;
                    o.x = (rok && cok0) ? vx : 0.0f;
                    o.y = (rok && cok1) ? vy : 0.0f;
                    blur2[r * (WB / 2) + p] = o;
                }
            }
        }
    }
    __syncthreads();

    // ---- stage 2: sobel -> mag + gx,gy cached; 18 pairs x 9 row-blocks ----
    {
        const float2* blur2 = (const float2*)s_blur;
        float2* mag2 = (float2*)s_mag;
        float2* gx2  = (float2*)s_gx;
        float2* gy2  = (float2*)s_gy;
        for (int idx = tid; idx < 18 * 9; idx += NT) {
            int p = idx % 18, rb = idx / 18;
            int rr = rb * 4;
            float P0[6], P1[6], Q0[6], Q1[6];
            #pragma unroll
            for (int i = 0; i < 6; i++) {
                float2 e = blur2[(rr + i) * (WB / 2) + p];
                float2 f = blur2[(rr + i) * (WB / 2) + p + 1];
                float a = e.x, bb = e.y, cc = f.x, d = f.y;
                P0[i] = a - cc;          P1[i] = bb - d;
                Q0[i] = a + 2.0f*bb + cc; Q1[i] = bb + 2.0f*cc + d;
            }
            int gxp0 = bx - 2 + 2 * p;
            bool cok0 = (unsigned)gxp0 < IMG_W;
            bool cok1 = (unsigned)(gxp0 + 1) < IMG_W;
            #pragma unroll
            for (int i = 0; i < 4; i++) {
                int r = rr + i;
                float gxa = P0[i] + 2.0f*P0[i+1] + P0[i+2];
                float gya = Q0[i] - Q0[i+2];
                float gxb = P1[i] + 2.0f*P1[i+1] + P1[i+2];
                float gyb = Q1[i] - Q1[i+2];
                float ma = sqrtf(gxa*gxa + gya*gya);
                float mb = sqrtf(gxb*gxb + gyb*gyb);
                int gy = by - 2 + r;
                bool rok = (unsigned)gy < IMG_H;
                float2 om;
                om.x = (rok && cok0) ? ma : 0.0f;
                om.y = (rok && cok1) ? mb : 0.0f;
                mag2[r * (WM / 2) + p] = om;
                gx2 [r * (WM / 2) + p] = make_float2(gxa, gxb);
                gy2 [r * (WM / 2) + p] = make_float2(gya, gyb);
            }
        }
    }
    __syncthreads();

    // ---- stage 3: non-max suppression -> thin; 17 pairs x 9 row-blocks ----
    {
        const float2* mag2 = (const float2*)s_mag;
        float2* thin2 = (float2*)s_thin;
        for (int idx = tid; idx < 17 * 9; idx += NT) {
            int p = idx % 17, rb = idx / 17;
            int rr = rb * 4;
            float P0[6], P1[6], Q0[6], Q1[6], MB[6], MC[6];
            #pragma unroll
            for (int i = 0; i < 6; i++) {
                float2 e = make_float2(0.f, 0.f), f = make_float2(0.f, 0.f);
                if (rr + i < 36) {
                    e = mag2[(rr + i) * (WM / 2) + p];
                    f = mag2[(rr + i) * (WM / 2) + p + 1];
                }
                float a = e.x, bb = e.y, cc = f.x, d = f.y;
                P0[i] = a - cc;           P1[i] = bb - d;
                Q0[i] = a + 2.0f*bb + cc; Q1[i] = bb + 2.0f*cc + d;
                MB[i] = bb; MC[i] = cc;
            }
            int gxp0 = bx - 1 + 2 * p;
            bool cok0 = (unsigned)gxp0 < IMG_W;
            bool cok1 = (unsigned)(gxp0 + 1) < IMG_W;
            #pragma unroll
            for (int i = 0; i < 4; i++) {
                int r = rr + i;
                if (r < 34) {
                    float sxa = P0[i] + 2.0f*P0[i+1] + P0[i+2];
                    float sya = Q0[i] - Q0[i+2];
                    float ma  = MB[i+1];
                    float va = (ma >= sxa && ma >= sya) ? ma : 0.0f;
                    float sxb = P1[i] + 2.0f*P1[i+1] + P1[i+2];
                    float syb = Q1[i] - Q1[i+2];
                    float mbv = MC[i+1];
                    float vb = (mbv >= sxb && mbv >= syb) ? mbv : 0.0f;
                    int gy = by - 1 + r;
                    bool rok = (unsigned)gy < IMG_H;
                    float2 o;
                    o.x = (rok && cok0) ? va : 0.0f;
                    o.y = (rok && cok1) ? vb : 0.0f;
                    thin2[r * (WN / 2) + p] = o;
                }
            }
        }
    }
    __syncthreads();

    // ---- stage 4: hysteresis + 5 plane writes; 1 column x 4 rows per thread ----
    {
        int c  = tid & 31;        // output column
        int rb = tid >> 5;        // row block (0..7)
        int rr = rb * 4;

        int sb[6][3];
        #pragma unroll
        for (int i = 0; i < 6; i++) {
            const float* row = s_thin + (rr + i) * WN + c;
            sb[i][0] = row[0] > 3.0f;
            sb[i][1] = row[1] > 3.0f;
            sb[i][2] = row[2] > 3.0f;
        }

        long long obase = (long long)b * (IMG_H * IMG_W)
                        + (long long)(by + rr) * IMG_W + (bx + c);
        #pragma unroll
        for (int i = 0; i < 4; i++) {
            float blv = s_blur[(rr + i + 3) * WB + (c + 3)];
            float mv  = s_mag [(rr + i + 2) * WM + (c + 2)];
            float gxv = s_gx  [(rr + i + 2) * WM + (c + 2)];
            float gyv = s_gy  [(rr + i + 2) * WM + (c + 2)];
            float tc  = s_thin[(rr + i + 1) * WN + (c + 1)];

            bool strong = tc > 3.0f;
            bool weak   = (tc > 1.0f) && (tc <= 3.0f);
            int full9 = sb[i][0] + sb[i][1] + sb[i][2]
                      + sb[i+1][0] + sb[i+1][1] + sb[i+1][2]
                      + sb[i+2][0] + sb[i+2][1] + sb[i+2][2];
            // conv with hyst_k (center -8) > 0  <=>  full9 - 9*center_strong > 0
            bool sn   = (full9 - 9 * sb[i+1][1]) > 0;
            bool edge = strong || (weak && sn);

            long long o = obase + (long long)i * IMG_W;
            out[o]         = blv;
            out[N + o]     = mv;
            out[2 * N + o] = fast_atan2(gyv, gxv);
            out[3 * N + o] = tc;
            out[4 * N + o] = edge ? 1.0f : 0.0f;
        }
    }
}

extern "C" void kernel_launch(void* const* d_in, const int* in_sizes, int n_in,
                              void* d_out, int out_size) {
    const float* img = (const float*)d_in[0];
    const float* gk  = (const float*)d_in[1];
    float* out = (float*)d_out;
    long long N = (long long)out_size / 5;   // 5 concatenated planes
    dim3 grid(IMG_W / TILE, IMG_H / TILE, BATCH);
    canny_kernel<<<grid, NT>>>(img, gk, out, N);
}